// round 10
// baseline (speedup 1.0000x reference)
#include <cuda_runtime.h>
#include <cuda_bf16.h>
#include <cuda_fp16.h>
#include <cstdint>

#define S_LEN 512
#define BATCH 64
#define D_IN  512
#define H_DIM 1024
#define G4    4096
#define M_ROWS 32768
#define NBLK  128

// ---- recurrence SMEM layout (bytes) ----
// W: 16 chunks x (32 rows x 144B) hi then lo (fp16)
#define RSM_WLO   73728
#define RSM_H     147456            // 3 bufs x 9216 (single fp16 h image)
#define RSM_G     175104            // gates 64x32 f32
#define RSM_TOTAL 183296
// ---- gx GEMM SMEM: 3 bufs x 73728 (Ahi,Alo,Bhi,Blo @ 18432 each) ----
#define GSM_TOTAL 221184

// ---------------- device scratch ----------------
__device__ float g_bh_p[G4];
__device__ float g_gx[(size_t)M_ROWS * G4];
__device__ __nv_bfloat16 g_x_hi[(size_t)M_ROWS * D_IN];
__device__ __nv_bfloat16 g_x_lo[(size_t)M_ROWS * D_IN];
__device__ __nv_bfloat16 g_Wxb_hi[(size_t)G4 * D_IN];   // n-major, permuted
__device__ __nv_bfloat16 g_Wxb_lo[(size_t)G4 * D_IN];
__device__ __half g_Wr_hi[(size_t)NBLK * 36864];        // per-CTA padded chunk images (fp16)
__device__ __half g_Wr_lo[(size_t)NBLK * 36864];
__device__ __half g_h[2][BATCH * H_DIM];                // single fp16 h image, ping-pong
__device__ unsigned g_flag[NBLK];                       // per-CTA publish counters (reset each launch)

// ---------------- helpers ----------------
__device__ __forceinline__ uint32_t smem_u32(const void* p) {
    uint32_t a;
    asm("{ .reg .u64 t; cvta.to.shared.u64 t, %1; cvt.u32.u64 %0, t; }" : "=r"(a) : "l"(p));
    return a;
}
__device__ __forceinline__ void ldm4(uint32_t a, uint32_t& r0, uint32_t& r1, uint32_t& r2, uint32_t& r3) {
    asm volatile("ldmatrix.sync.aligned.m8n8.x4.shared.b16 {%0,%1,%2,%3}, [%4];"
                 : "=r"(r0), "=r"(r1), "=r"(r2), "=r"(r3) : "r"(a));
}
__device__ __forceinline__ void mma_bf16(float* c, uint32_t a0, uint32_t a1, uint32_t a2, uint32_t a3,
                                         uint32_t b0, uint32_t b1) {
    asm volatile("mma.sync.aligned.m16n8k16.row.col.f32.bf16.bf16.f32 "
                 "{%0,%1,%2,%3}, {%4,%5,%6,%7}, {%8,%9}, {%0,%1,%2,%3};"
                 : "+f"(c[0]), "+f"(c[1]), "+f"(c[2]), "+f"(c[3])
                 : "r"(a0), "r"(a1), "r"(a2), "r"(a3), "r"(b0), "r"(b1));
}
__device__ __forceinline__ void mma_f16(float* c, uint32_t a0, uint32_t a1, uint32_t a2, uint32_t a3,
                                        uint32_t b0, uint32_t b1) {
    asm volatile("mma.sync.aligned.m16n8k16.row.col.f32.f16.f16.f32 "
                 "{%0,%1,%2,%3}, {%4,%5,%6,%7}, {%8,%9}, {%0,%1,%2,%3};"
                 : "+f"(c[0]), "+f"(c[1]), "+f"(c[2]), "+f"(c[3])
                 : "r"(a0), "r"(a1), "r"(a2), "r"(a3), "r"(b0), "r"(b1));
}
__device__ __forceinline__ void cp16(uint32_t dst, const void* src) {
    asm volatile("cp.async.cg.shared.global [%0], [%1], 16;" :: "r"(dst), "l"(src) : "memory");
}
__device__ __forceinline__ void cp_commit() { asm volatile("cp.async.commit_group;" ::: "memory"); }
__device__ __forceinline__ void cp_wait1()  { asm volatile("cp.async.wait_group 1;" ::: "memory"); }
__device__ __forceinline__ void cp_wait0()  { asm volatile("cp.async.wait_group 0;" ::: "memory"); }
__device__ __forceinline__ float sigm(float x) { return 1.0f / (1.0f + __expf(-x)); }

__device__ __forceinline__ unsigned ld_acq(const unsigned* p) {
    unsigned v;
    asm volatile("ld.acquire.gpu.global.u32 %0, [%1];" : "=r"(v) : "l"(p) : "memory");
    return v;
}
__device__ __forceinline__ void flag_wait(const unsigned* p, unsigned want) {
    if (ld_acq(p) >= want) return;
    while (ld_acq(p) < want) __nanosleep(20);
}

// ---------------- prep: Wx -> n-major permuted bf16 hi/lo; bias; flag reset ----
__global__ void prep_wxb(const float* __restrict__ Wx, const float* __restrict__ bh) {
    if (blockIdx.x == 0 && threadIdx.x < NBLK)
        *(volatile unsigned*)&g_flag[threadIdx.x] = 0u;
    int idx = blockIdx.x * blockDim.x + threadIdx.x;      // 4096*512
    if (idx >= G4 * D_IN) return;
    int n = idx >> 9, k = idx & 511;
    float v = Wx[(size_t)k * G4 + (n & 3) * H_DIM + (n >> 2)];
    __nv_bfloat16 hi = __float2bfloat16(v);
    g_Wxb_hi[idx] = hi;
    g_Wxb_lo[idx] = __float2bfloat16(v - __bfloat162float(hi));
    if (k == 0) g_bh_p[n] = bh[(n & 3) * H_DIM + (n >> 2)];
}

// ---------------- prep: x -> bf16 hi/lo ----------------
__global__ void conv_x(const float* __restrict__ x) {
    size_t idx = (size_t)blockIdx.x * blockDim.x + threadIdx.x;
    if (idx >= (size_t)M_ROWS * D_IN) return;
    float v = x[idx];
    __nv_bfloat16 hi = __float2bfloat16(v);
    g_x_hi[idx] = hi;
    g_x_lo[idx] = __float2bfloat16(v - __bfloat162float(hi));
}

// ---------------- prep: per-CTA padded W chunk images (fp16 hi/lo) ----------------
// image: 16 chunks x (32 n-rows x 72 elems [64 data + 8 pad])
__global__ void prep_wrec(const float* __restrict__ Wh) {
    size_t idx = (size_t)blockIdx.x * blockDim.x + threadIdx.x;
    if (idx >= (size_t)NBLK * 36864) return;
    int bid = (int)(idx / 36864);
    int e = (int)(idx % 36864);
    int c = e / 2304, rr = e % 2304;
    int n = rr / 72, k = rr % 72;
    __half hi = __float2half(0.f), lo = __float2half(0.f);
    if (k < 64) {
        int cn = bid * 32 + n;
        float v = Wh[(size_t)(c * 64 + k) * G4 + (cn & 3) * H_DIM + (cn >> 2)];
        hi = __float2half(v);
        lo = __float2half(v - __half2float(hi));
    }
    g_Wr_hi[idx] = hi;
    g_Wr_lo[idx] = lo;
}

// ---------------- gx GEMM (mma.sync bf16 3-term): g_gx = x @ Wx_p ----------------
__global__ __launch_bounds__(512, 1) void gemm_gx() {
    extern __shared__ char smem[];
    const uint32_t sb = smem_u32(smem);
    const int tid = threadIdx.x, lane = tid & 31, w = tid >> 5;
    const int mB = blockIdx.y * 128, nB = blockIdx.x * 128;
    const int m0 = (w & 3) * 32, n0 = (w >> 2) * 32;

    float acc[2][4][4];
#pragma unroll
    for (int a = 0; a < 2; ++a)
#pragma unroll
        for (int b = 0; b < 4; ++b)
#pragma unroll
            for (int d = 0; d < 4; ++d) acc[a][b][d] = 0.f;

    uint32_t aoff[2], boff[2];
#pragma unroll
    for (int mt = 0; mt < 2; ++mt)
        aoff[mt] = (uint32_t)(m0 + mt * 16 + (lane & 15)) * 144u + (uint32_t)(lane >> 4) * 16u;
#pragma unroll
    for (int g = 0; g < 2; ++g)
        boff[g] = (uint32_t)(n0 + g * 16 + ((lane >> 4) << 3) + (lane & 7)) * 144u +
                  (uint32_t)((lane >> 3) & 1) * 16u;

#define GX_ISSUE(ch, buf) do {                                                     \
    _Pragma("unroll")                                                              \
    for (int q = 0; q < 8; ++q) {                                                  \
        int id = tid + q * 512;                                                    \
        int arr = id >> 10, rem = id & 1023, row = rem >> 3, seg = rem & 7;        \
        uint32_t dst = sb + (uint32_t)(buf) * 73728u + (uint32_t)arr * 18432u +    \
                       (uint32_t)row * 144u + (uint32_t)seg * 16u;                 \
        const __nv_bfloat16* src;                                                  \
        if (arr == 0)      src = g_x_hi + (size_t)(mB + row) * 512;                \
        else if (arr == 1) src = g_x_lo + (size_t)(mB + row) * 512;                \
        else if (arr == 2) src = g_Wxb_hi + (size_t)(nB + row) * 512;              \
        else               src = g_Wxb_lo + (size_t)(nB + row) * 512;              \
        cp16(dst, src + (ch) * 64 + seg * 8);                                      \
    }                                                                              \
    cp_commit();                                                                   \
} while (0)

    GX_ISSUE(0, 0);
    GX_ISSUE(1, 1);
    for (int c = 0; c < 8; ++c) {
        if (c < 7) cp_wait1(); else cp_wait0();
        __syncthreads();
        const uint32_t base = sb + (uint32_t)(c % 3) * 73728u;
#pragma unroll
        for (int kk = 0; kk < 4; ++kk) {
            const uint32_t o = kk * 32;
            uint32_t ah[2][4], al[2][4], bhv[2][4], blv[2][4];
#pragma unroll
            for (int mt = 0; mt < 2; ++mt) {
                ldm4(base + aoff[mt] + o, ah[mt][0], ah[mt][1], ah[mt][2], ah[mt][3]);
                ldm4(base + 18432u + aoff[mt] + o, al[mt][0], al[mt][1], al[mt][2], al[mt][3]);
            }
#pragma unroll
            for (int g = 0; g < 2; ++g) {
                ldm4(base + 36864u + boff[g] + o, bhv[g][0], bhv[g][1], bhv[g][2], bhv[g][3]);
                ldm4(base + 55296u + boff[g] + o, blv[g][0], blv[g][1], blv[g][2], blv[g][3]);
            }
#pragma unroll
            for (int mt = 0; mt < 2; ++mt)
#pragma unroll
                for (int g = 0; g < 2; ++g) {
                    mma_bf16(acc[mt][g * 2],     ah[mt][0], ah[mt][1], ah[mt][2], ah[mt][3], bhv[g][0], bhv[g][1]);
                    mma_bf16(acc[mt][g * 2 + 1], ah[mt][0], ah[mt][1], ah[mt][2], ah[mt][3], bhv[g][2], bhv[g][3]);
                }
#pragma unroll
            for (int mt = 0; mt < 2; ++mt)
#pragma unroll
                for (int g = 0; g < 2; ++g) {
                    mma_bf16(acc[mt][g * 2],     al[mt][0], al[mt][1], al[mt][2], al[mt][3], bhv[g][0], bhv[g][1]);
                    mma_bf16(acc[mt][g * 2 + 1], al[mt][0], al[mt][1], al[mt][2], al[mt][3], bhv[g][2], bhv[g][3]);
                }
#pragma unroll
            for (int mt = 0; mt < 2; ++mt)
#pragma unroll
                for (int g = 0; g < 2; ++g) {
                    mma_bf16(acc[mt][g * 2],     ah[mt][0], ah[mt][1], ah[mt][2], ah[mt][3], blv[g][0], blv[g][1]);
                    mma_bf16(acc[mt][g * 2 + 1], ah[mt][0], ah[mt][1], ah[mt][2], ah[mt][3], blv[g][2], blv[g][3]);
                }
        }
        __syncthreads();
        if (c < 6) GX_ISSUE(c + 2, (c + 2) % 3);
    }
#undef GX_ISSUE
#pragma unroll
    for (int mt = 0; mt < 2; ++mt)
#pragma unroll
        for (int g = 0; g < 2; ++g)
#pragma unroll
            for (int hf = 0; hf < 2; ++hf) {
                int m = mB + m0 + mt * 16 + (lane >> 2);
                int n = nB + n0 + g * 16 + hf * 8 + (lane & 3) * 2;
                float* f = acc[mt][g * 2 + hf];
                *(float2*)&g_gx[(size_t)m * G4 + n] = make_float2(f[0], f[1]);
                *(float2*)&g_gx[(size_t)(m + 8) * G4 + n] = make_float2(f[2], f[3]);
            }
}

// ---------------- persistent mma.sync recurrence (fp16 2-term, flag sync) --------
__global__ __launch_bounds__(256, 1) void lstm_rec(const float* __restrict__ h0,
                                                   const float* __restrict__ c0,
                                                   float* __restrict__ out) {
    extern __shared__ char smem[];
    const uint32_t sb = smem_u32(smem);
    const int tid = threadIdx.x, lane = tid & 31, w = tid >> 5, bid = blockIdx.x;
    const int hcb = bid * 8;
    const int m0 = (w & 3) * 16, n0 = (w >> 2) * 16;

    // resident W slice (fp16 hi + lo)
    {
        const int4* swh = (const int4*)(g_Wr_hi + (size_t)bid * 36864);
        const int4* swl = (const int4*)(g_Wr_lo + (size_t)bid * 36864);
        int4* dh = (int4*)smem;
        int4* dl = (int4*)(smem + RSM_WLO);
        for (int i = tid; i < 4608; i += 256) { dh[i] = swh[i]; dl[i] = swl[i]; }
    }
    // h0 -> fp16 ping buffer 0 — OWNED columns only (all 64 batch rows, cols hcb..hcb+7)
    for (int i = tid; i < 512; i += 256) {
        int b = i >> 3, col = hcb + (i & 7);
        g_h[0][b * H_DIM + col] = __float2half(h0[b * H_DIM + col]);
    }
    // per-thread cell state + bias
    const int eb = tid >> 3, ehl = tid & 7;
    float c_r[2];
    c_r[0] = c0[eb * H_DIM + hcb + ehl];
    c_r[1] = c0[(eb + 32) * H_DIM + hcb + ehl];
    const float4 br = *(const float4*)&g_bh_p[bid * 32 + ehl * 4];

    const uint32_t a_off = (uint32_t)(m0 + (lane & 15)) * 144u + (uint32_t)(lane >> 4) * 16u;
    const uint32_t b_off = (uint32_t)(n0 + ((lane >> 4) << 3) + (lane & 7)) * 144u +
                           (uint32_t)((lane >> 3) & 1) * 16u;
    const int my_seg = tid & 7;   // h-column segment this thread's cp.async loads

    // publish h^0
    __syncthreads();
    if (tid == 0) { __threadfence(); *(volatile unsigned*)&g_flag[bid] = 1u; }

    for (int t = 0; t < S_LEN; ++t) {
        const int nb = t & 1;
        const unsigned fneed = (unsigned)t + 1u;   // h^t published
        // prefetch gx (raw, bias added below)
        float4 gv0 = *(const float4*)&g_gx[(size_t)(t * BATCH + eb) * G4 + bid * 32 + ehl * 4];
        float4 gv1 = *(const float4*)&g_gx[(size_t)(t * BATCH + eb + 32) * G4 + bid * 32 + ehl * 4];

        // 4 independent accumulators: {acc0,acc1} x {W_hi, W_lo} terms
        float a0h[4] = {0.f, 0.f, 0.f, 0.f}, a0c[4] = {0.f, 0.f, 0.f, 0.f};
        float a1h[4] = {0.f, 0.f, 0.f, 0.f}, a1c[4] = {0.f, 0.f, 0.f, 0.f};

#define H_ISSUE(ch, buf) do {                                                      \
    flag_wait(&g_flag[(ch) * 8 + my_seg], fneed);                                  \
    _Pragma("unroll")                                                              \
    for (int q = 0; q < 2; ++q) {                                                  \
        int id = tid + q * 256;                                                    \
        int row = id >> 3, seg = id & 7;                                           \
        uint32_t dst = sb + RSM_H + (uint32_t)(buf) * 9216u +                      \
                       (uint32_t)row * 144u + (uint32_t)seg * 16u;                 \
        const __half* src = g_h[nb] + row * H_DIM + (ch) * 64 + seg * 8;           \
        cp16(dst, src);                                                            \
    }                                                                              \
    cp_commit();                                                                   \
} while (0)

        H_ISSUE(0, 0);
        H_ISSUE(1, 1);
        for (int c = 0; c < 16; ++c) {
            if (c < 15) cp_wait1(); else cp_wait0();
            __syncthreads();
            const uint32_t ah = sb + RSM_H + (uint32_t)(c % 3) * 9216u + a_off;
            const uint32_t bh = sb + (uint32_t)c * 4608u + b_off;
            const uint32_t bl = bh + RSM_WLO;
#pragma unroll
            for (int kk = 0; kk < 4; ++kk) {
                const uint32_t o = kk * 32;
                uint32_t A0, A1, A2, A3;
                uint32_t B0, B1, B2, B3, C0, C1, C2, C3;
                ldm4(ah + o, A0, A1, A2, A3);
                ldm4(bh + o, B0, B1, B2, B3);
                ldm4(bl + o, C0, C1, C2, C3);
                mma_f16(a0h, A0, A1, A2, A3, B0, B1);
                mma_f16(a1h, A0, A1, A2, A3, B2, B3);
                mma_f16(a0c, A0, A1, A2, A3, C0, C1);
                mma_f16(a1c, A0, A1, A2, A3, C2, C3);
            }
            if (c < 14) H_ISSUE(c + 2, (c + 2) % 3);
        }
#undef H_ISSUE

        // reduce terms and stage gates
        {
            float* G = (float*)(smem + RSM_G);
            int r0 = m0 + (lane >> 2), cb0 = n0 + (lane & 3) * 2;
            float s00 = a0h[0] + a0c[0], s01 = a0h[1] + a0c[1];
            float s02 = a0h[2] + a0c[2], s03 = a0h[3] + a0c[3];
            float s10 = a1h[0] + a1c[0], s11 = a1h[1] + a1c[1];
            float s12 = a1h[2] + a1c[2], s13 = a1h[3] + a1c[3];
            *(float2*)&G[r0 * 32 + cb0]           = make_float2(s00, s01);
            *(float2*)&G[(r0 + 8) * 32 + cb0]     = make_float2(s02, s03);
            *(float2*)&G[r0 * 32 + cb0 + 8]       = make_float2(s10, s11);
            *(float2*)&G[(r0 + 8) * 32 + cb0 + 8] = make_float2(s12, s13);
        }
        __syncthreads();

        // elementwise LSTM for (eb, ehl) and (eb+32, ehl)
        const int nb2 = nb ^ 1;
        const float* G = (const float*)(smem + RSM_G);
#pragma unroll
        for (int q = 0; q < 2; ++q) {
            int b = eb + q * 32;
            float4 gr = *(const float4*)&G[b * 32 + ehl * 4];
            float4 gx = q ? gv1 : gv0;
            float gi = gr.x + gx.x + br.x;
            float gf = gr.y + gx.y + br.y;
            float gj = gr.z + gx.z + br.z;
            float go = gr.w + gx.w + br.w;
            float cn = c_r[q] * sigm(gf + 1.0f) + sigm(gi) * tanhf(gj);
            c_r[q] = cn;
            float hn = tanhf(cn) * sigm(go);
            g_h[nb2][b * H_DIM + hcb + ehl] = __float2half(hn);
            if (t == S_LEN - 1) {
                out[b * H_DIM + hcb + ehl] = hn;
                out[BATCH * H_DIM + b * H_DIM + hcb + ehl] = cn;
            }
        }
        // publish h^{t+1} (skip after last step)
        if (t + 1 < S_LEN) {
            __syncthreads();
            if (tid == 0) { __threadfence(); *(volatile unsigned*)&g_flag[bid] = (unsigned)t + 2u; }
        }
    }
}

// ---------------- host launch ----------------
extern "C" void kernel_launch(void* const* d_in, const int* in_sizes, int n_in,
                              void* d_out, int out_size) {
    const float* x  = (const float*)d_in[0];
    const float* h0 = (const float*)d_in[1];
    const float* c0 = (const float*)d_in[2];
    const float* Wx = (const float*)d_in[3];
    const float* Wh = (const float*)d_in[4];
    const float* bh = (const float*)d_in[5];
    float* out = (float*)d_out;

    prep_wxb<<<(G4 * D_IN + 255) / 256, 256>>>(Wx, bh);
    conv_x<<<(M_ROWS * D_IN + 511) / 512, 512>>>(x);
    prep_wrec<<<(NBLK * 36864 + 255) / 256, 256>>>(Wh);
    cudaFuncSetAttribute(gemm_gx, cudaFuncAttributeMaxDynamicSharedMemorySize, GSM_TOTAL);
    gemm_gx<<<dim3(G4 / 128, M_ROWS / 128), 512, GSM_TOTAL>>>();
    cudaFuncSetAttribute(lstm_rec, cudaFuncAttributeMaxDynamicSharedMemorySize, RSM_TOTAL);
    lstm_rec<<<NBLK, 256, RSM_TOTAL>>>(h0, c0, out);
}

// round 11
// speedup vs baseline: 1.3402x; 1.3402x over previous
#include <cuda_runtime.h>
#include <cuda_bf16.h>
#include <cuda_fp16.h>
#include <cstdint>

#define S_LEN 512
#define BATCH 64
#define D_IN  512
#define H_DIM 1024
#define G4    4096
#define M_ROWS 32768
#define NBLK  128

// ---- recurrence SMEM layout (bytes) ----
// W: 16 chunks x (32 rows x 144B), single fp16 image
#define RSM_H     73728             // 3 bufs x 9216 (single fp16 h image)
#define RSM_G     101376            // gates 64x32 f32
#define RSM_TOTAL 109568
// ---- gx GEMM SMEM: 3 bufs x 73728 (Ahi,Alo,Bhi,Blo @ 18432 each) ----
#define GSM_TOTAL 221184

// ---------------- device scratch ----------------
__device__ float g_bh_p[G4];
__device__ float g_gx[(size_t)M_ROWS * G4];
__device__ __nv_bfloat16 g_x_hi[(size_t)M_ROWS * D_IN];
__device__ __nv_bfloat16 g_x_lo[(size_t)M_ROWS * D_IN];
__device__ __nv_bfloat16 g_Wxb_hi[(size_t)G4 * D_IN];   // n-major, permuted
__device__ __nv_bfloat16 g_Wxb_lo[(size_t)G4 * D_IN];
__device__ __half g_Wr[(size_t)NBLK * 36864];           // per-CTA padded chunk images (fp16)
__device__ __half g_h[2][BATCH * H_DIM];                // single fp16 h image, ping-pong
__device__ unsigned g_bar_count, g_bar_gen;

// ---------------- helpers ----------------
__device__ __forceinline__ uint32_t smem_u32(const void* p) {
    uint32_t a;
    asm("{ .reg .u64 t; cvta.to.shared.u64 t, %1; cvt.u32.u64 %0, t; }" : "=r"(a) : "l"(p));
    return a;
}
__device__ __forceinline__ void ldm4(uint32_t a, uint32_t& r0, uint32_t& r1, uint32_t& r2, uint32_t& r3) {
    asm volatile("ldmatrix.sync.aligned.m8n8.x4.shared.b16 {%0,%1,%2,%3}, [%4];"
                 : "=r"(r0), "=r"(r1), "=r"(r2), "=r"(r3) : "r"(a));
}
__device__ __forceinline__ void mma_bf16(float* c, uint32_t a0, uint32_t a1, uint32_t a2, uint32_t a3,
                                         uint32_t b0, uint32_t b1) {
    asm volatile("mma.sync.aligned.m16n8k16.row.col.f32.bf16.bf16.f32 "
                 "{%0,%1,%2,%3}, {%4,%5,%6,%7}, {%8,%9}, {%0,%1,%2,%3};"
                 : "+f"(c[0]), "+f"(c[1]), "+f"(c[2]), "+f"(c[3])
                 : "r"(a0), "r"(a1), "r"(a2), "r"(a3), "r"(b0), "r"(b1));
}
__device__ __forceinline__ void mma_f16(float* c, uint32_t a0, uint32_t a1, uint32_t a2, uint32_t a3,
                                        uint32_t b0, uint32_t b1) {
    asm volatile("mma.sync.aligned.m16n8k16.row.col.f32.f16.f16.f32 "
                 "{%0,%1,%2,%3}, {%4,%5,%6,%7}, {%8,%9}, {%0,%1,%2,%3};"
                 : "+f"(c[0]), "+f"(c[1]), "+f"(c[2]), "+f"(c[3])
                 : "r"(a0), "r"(a1), "r"(a2), "r"(a3), "r"(b0), "r"(b1));
}
__device__ __forceinline__ void cp16(uint32_t dst, const void* src) {
    asm volatile("cp.async.cg.shared.global [%0], [%1], 16;" :: "r"(dst), "l"(src) : "memory");
}
__device__ __forceinline__ void cp_commit() { asm volatile("cp.async.commit_group;" ::: "memory"); }
__device__ __forceinline__ void cp_wait1()  { asm volatile("cp.async.wait_group 1;" ::: "memory"); }
__device__ __forceinline__ void cp_wait0()  { asm volatile("cp.async.wait_group 0;" ::: "memory"); }
__device__ __forceinline__ float sigm(float x) { return 1.0f / (1.0f + __expf(-x)); }

__device__ __forceinline__ void grid_sync(unsigned& bar) {
    __syncthreads();
    if (threadIdx.x == 0) {
        __threadfence();
        unsigned t = atomicAdd(&g_bar_count, 1u);
        bar += 1;
        if (t == gridDim.x - 1u) {
            atomicExch(&g_bar_count, 0u);
            __threadfence();
            atomicAdd(&g_bar_gen, 1u);
        } else {
            while ((int)(atomicAdd(&g_bar_gen, 0u) - bar) < 0) __nanosleep(64);
        }
    }
    __syncthreads();
}

// ---------------- prep: Wx -> n-major permuted bf16 hi/lo; bias ----------------
__global__ void prep_wxb(const float* __restrict__ Wx, const float* __restrict__ bh) {
    int idx = blockIdx.x * blockDim.x + threadIdx.x;      // 4096*512
    if (idx >= G4 * D_IN) return;
    int n = idx >> 9, k = idx & 511;
    float v = Wx[(size_t)k * G4 + (n & 3) * H_DIM + (n >> 2)];
    __nv_bfloat16 hi = __float2bfloat16(v);
    g_Wxb_hi[idx] = hi;
    g_Wxb_lo[idx] = __float2bfloat16(v - __bfloat162float(hi));
    if (k == 0) g_bh_p[n] = bh[(n & 3) * H_DIM + (n >> 2)];
}

// ---------------- prep: x -> bf16 hi/lo ----------------
__global__ void conv_x(const float* __restrict__ x) {
    size_t idx = (size_t)blockIdx.x * blockDim.x + threadIdx.x;
    if (idx >= (size_t)M_ROWS * D_IN) return;
    float v = x[idx];
    __nv_bfloat16 hi = __float2bfloat16(v);
    g_x_hi[idx] = hi;
    g_x_lo[idx] = __float2bfloat16(v - __bfloat162float(hi));
}

// ---------------- prep: per-CTA padded W chunk images (single fp16) ----------------
// image: 16 chunks x (32 n-rows x 72 elems [64 data + 8 pad])
__global__ void prep_wrec(const float* __restrict__ Wh) {
    size_t idx = (size_t)blockIdx.x * blockDim.x + threadIdx.x;
    if (idx >= (size_t)NBLK * 36864) return;
    int bid = (int)(idx / 36864);
    int e = (int)(idx % 36864);
    int c = e / 2304, rr = e % 2304;
    int n = rr / 72, k = rr % 72;
    __half hi = __float2half(0.f);
    if (k < 64) {
        int cn = bid * 32 + n;
        hi = __float2half(Wh[(size_t)(c * 64 + k) * G4 + (cn & 3) * H_DIM + (cn >> 2)]);
    }
    g_Wr[idx] = hi;
}

// ---------------- gx GEMM (mma.sync bf16 3-term): g_gx = x @ Wx_p ----------------
__global__ __launch_bounds__(512, 1) void gemm_gx() {
    extern __shared__ char smem[];
    const uint32_t sb = smem_u32(smem);
    const int tid = threadIdx.x, lane = tid & 31, w = tid >> 5;
    const int mB = blockIdx.y * 128, nB = blockIdx.x * 128;
    const int m0 = (w & 3) * 32, n0 = (w >> 2) * 32;

    float acc[2][4][4];
#pragma unroll
    for (int a = 0; a < 2; ++a)
#pragma unroll
        for (int b = 0; b < 4; ++b)
#pragma unroll
            for (int d = 0; d < 4; ++d) acc[a][b][d] = 0.f;

    uint32_t aoff[2], boff[2];
#pragma unroll
    for (int mt = 0; mt < 2; ++mt)
        aoff[mt] = (uint32_t)(m0 + mt * 16 + (lane & 15)) * 144u + (uint32_t)(lane >> 4) * 16u;
#pragma unroll
    for (int g = 0; g < 2; ++g)
        boff[g] = (uint32_t)(n0 + g * 16 + ((lane >> 4) << 3) + (lane & 7)) * 144u +
                  (uint32_t)((lane >> 3) & 1) * 16u;

#define GX_ISSUE(ch, buf) do {                                                     \
    _Pragma("unroll")                                                              \
    for (int q = 0; q < 8; ++q) {                                                  \
        int id = tid + q * 512;                                                    \
        int arr = id >> 10, rem = id & 1023, row = rem >> 3, seg = rem & 7;        \
        uint32_t dst = sb + (uint32_t)(buf) * 73728u + (uint32_t)arr * 18432u +    \
                       (uint32_t)row * 144u + (uint32_t)seg * 16u;                 \
        const __nv_bfloat16* src;                                                  \
        if (arr == 0)      src = g_x_hi + (size_t)(mB + row) * 512;                \
        else if (arr == 1) src = g_x_lo + (size_t)(mB + row) * 512;                \
        else if (arr == 2) src = g_Wxb_hi + (size_t)(nB + row) * 512;              \
        else               src = g_Wxb_lo + (size_t)(nB + row) * 512;              \
        cp16(dst, src + (ch) * 64 + seg * 8);                                      \
    }                                                                              \
    cp_commit();                                                                   \
} while (0)

    GX_ISSUE(0, 0);
    GX_ISSUE(1, 1);
    for (int c = 0; c < 8; ++c) {
        if (c < 7) cp_wait1(); else cp_wait0();
        __syncthreads();
        const uint32_t base = sb + (uint32_t)(c % 3) * 73728u;
#pragma unroll
        for (int kk = 0; kk < 4; ++kk) {
            const uint32_t o = kk * 32;
            uint32_t ah[2][4], al[2][4], bhv[2][4], blv[2][4];
#pragma unroll
            for (int mt = 0; mt < 2; ++mt) {
                ldm4(base + aoff[mt] + o, ah[mt][0], ah[mt][1], ah[mt][2], ah[mt][3]);
                ldm4(base + 18432u + aoff[mt] + o, al[mt][0], al[mt][1], al[mt][2], al[mt][3]);
            }
#pragma unroll
            for (int g = 0; g < 2; ++g) {
                ldm4(base + 36864u + boff[g] + o, bhv[g][0], bhv[g][1], bhv[g][2], bhv[g][3]);
                ldm4(base + 55296u + boff[g] + o, blv[g][0], blv[g][1], blv[g][2], blv[g][3]);
            }
#pragma unroll
            for (int mt = 0; mt < 2; ++mt)
#pragma unroll
                for (int g = 0; g < 2; ++g) {
                    mma_bf16(acc[mt][g * 2],     ah[mt][0], ah[mt][1], ah[mt][2], ah[mt][3], bhv[g][0], bhv[g][1]);
                    mma_bf16(acc[mt][g * 2 + 1], ah[mt][0], ah[mt][1], ah[mt][2], ah[mt][3], bhv[g][2], bhv[g][3]);
                }
#pragma unroll
            for (int mt = 0; mt < 2; ++mt)
#pragma unroll
                for (int g = 0; g < 2; ++g) {
                    mma_bf16(acc[mt][g * 2],     al[mt][0], al[mt][1], al[mt][2], al[mt][3], bhv[g][0], bhv[g][1]);
                    mma_bf16(acc[mt][g * 2 + 1], al[mt][0], al[mt][1], al[mt][2], al[mt][3], bhv[g][2], bhv[g][3]);
                }
#pragma unroll
            for (int mt = 0; mt < 2; ++mt)
#pragma unroll
                for (int g = 0; g < 2; ++g) {
                    mma_bf16(acc[mt][g * 2],     ah[mt][0], ah[mt][1], ah[mt][2], ah[mt][3], blv[g][0], blv[g][1]);
                    mma_bf16(acc[mt][g * 2 + 1], ah[mt][0], ah[mt][1], ah[mt][2], ah[mt][3], blv[g][2], blv[g][3]);
                }
        }
        __syncthreads();
        if (c < 6) GX_ISSUE(c + 2, (c + 2) % 3);
    }
#undef GX_ISSUE
#pragma unroll
    for (int mt = 0; mt < 2; ++mt)
#pragma unroll
        for (int g = 0; g < 2; ++g)
#pragma unroll
            for (int hf = 0; hf < 2; ++hf) {
                int m = mB + m0 + mt * 16 + (lane >> 2);
                int n = nB + n0 + g * 16 + hf * 8 + (lane & 3) * 2;
                float* f = acc[mt][g * 2 + hf];
                *(float2*)&g_gx[(size_t)m * G4 + n] = make_float2(f[0], f[1]);
                *(float2*)&g_gx[(size_t)(m + 8) * G4 + n] = make_float2(f[2], f[3]);
            }
}

// ---------------- persistent mma.sync recurrence (fp16 single-W) ----------------
__global__ __launch_bounds__(256, 1) void lstm_rec(const float* __restrict__ h0,
                                                   const float* __restrict__ c0,
                                                   float* __restrict__ out) {
    extern __shared__ char smem[];
    const uint32_t sb = smem_u32(smem);
    const int tid = threadIdx.x, lane = tid & 31, w = tid >> 5, bid = blockIdx.x;
    const int hcb = bid * 8;
    const int m0 = (w & 3) * 16, n0 = (w >> 2) * 16;

    // resident W slice (single fp16)
    {
        const int4* sw = (const int4*)(g_Wr + (size_t)bid * 36864);
        int4* dw = (int4*)smem;
        for (int i = tid; i < 4608; i += 256) dw[i] = sw[i];
    }
    // h0 -> fp16 ping buffer 0 (disjoint slice per CTA)
    for (int i = tid; i < 512; i += 256) {
        int p = bid * 512 + i;
        g_h[0][p] = __float2half(h0[p]);
    }
    // per-thread cell state + bias
    const int eb = tid >> 3, ehl = tid & 7;
    float c_r[2];
    c_r[0] = c0[eb * H_DIM + hcb + ehl];
    c_r[1] = c0[(eb + 32) * H_DIM + hcb + ehl];
    const float4 br = *(const float4*)&g_bh_p[bid * 32 + ehl * 4];

    const uint32_t a_off = (uint32_t)(m0 + (lane & 15)) * 144u + (uint32_t)(lane >> 4) * 16u;
    const uint32_t b_off = (uint32_t)(n0 + ((lane >> 4) << 3) + (lane & 7)) * 144u +
                           (uint32_t)((lane >> 3) & 1) * 16u;

    unsigned bar = 0;
    if (tid == 0) bar = atomicAdd(&g_bar_gen, 0u);
    grid_sync(bar);

    for (int t = 0; t < S_LEN; ++t) {
        const int nb = t & 1;
        // prefetch gx (raw, bias added below)
        float4 gv0 = *(const float4*)&g_gx[(size_t)(t * BATCH + eb) * G4 + bid * 32 + ehl * 4];
        float4 gv1 = *(const float4*)&g_gx[(size_t)(t * BATCH + eb + 32) * G4 + bid * 32 + ehl * 4];

        // 2 independent accumulators (n-halves)
        float a0[4] = {0.f, 0.f, 0.f, 0.f};
        float a1[4] = {0.f, 0.f, 0.f, 0.f};

#define H_ISSUE(ch, buf) do {                                                      \
    _Pragma("unroll")                                                              \
    for (int q = 0; q < 2; ++q) {                                                  \
        int id = tid + q * 256;                                                    \
        int row = id >> 3, seg = id & 7;                                           \
        uint32_t dst = sb + RSM_H + (uint32_t)(buf) * 9216u +                      \
                       (uint32_t)row * 144u + (uint32_t)seg * 16u;                 \
        const __half* src = g_h[nb] + row * H_DIM + (ch) * 64 + seg * 8;           \
        cp16(dst, src);                                                            \
    }                                                                              \
    cp_commit();                                                                   \
} while (0)

        H_ISSUE(0, 0);
        H_ISSUE(1, 1);
        for (int c = 0; c < 16; ++c) {
            if (c < 15) cp_wait1(); else cp_wait0();
            __syncthreads();
            const uint32_t ah = sb + RSM_H + (uint32_t)(c % 3) * 9216u + a_off;
            const uint32_t bh = sb + (uint32_t)c * 4608u + b_off;
#pragma unroll
            for (int kk = 0; kk < 4; ++kk) {
                const uint32_t o = kk * 32;
                uint32_t A0, A1, A2, A3;
                uint32_t B0, B1, B2, B3;
                ldm4(ah + o, A0, A1, A2, A3);
                ldm4(bh + o, B0, B1, B2, B3);
                mma_f16(a0, A0, A1, A2, A3, B0, B1);
                mma_f16(a1, A0, A1, A2, A3, B2, B3);
            }
            if (c < 14) H_ISSUE(c + 2, (c + 2) % 3);
        }
#undef H_ISSUE

        // stage gates
        {
            float* G = (float*)(smem + RSM_G);
            int r0 = m0 + (lane >> 2), cb0 = n0 + (lane & 3) * 2;
            *(float2*)&G[r0 * 32 + cb0]           = make_float2(a0[0], a0[1]);
            *(float2*)&G[(r0 + 8) * 32 + cb0]     = make_float2(a0[2], a0[3]);
            *(float2*)&G[r0 * 32 + cb0 + 8]       = make_float2(a1[0], a1[1]);
            *(float2*)&G[(r0 + 8) * 32 + cb0 + 8] = make_float2(a1[2], a1[3]);
        }
        __syncthreads();

        // elementwise LSTM for (eb, ehl) and (eb+32, ehl)
        const int nb2 = nb ^ 1;
        const float* G = (const float*)(smem + RSM_G);
#pragma unroll
        for (int q = 0; q < 2; ++q) {
            int b = eb + q * 32;
            float4 gr = *(const float4*)&G[b * 32 + ehl * 4];
            float4 gx = q ? gv1 : gv0;
            float gi = gr.x + gx.x + br.x;
            float gf = gr.y + gx.y + br.y;
            float gj = gr.z + gx.z + br.z;
            float go = gr.w + gx.w + br.w;
            float cn = c_r[q] * sigm(gf + 1.0f) + sigm(gi) * tanhf(gj);
            c_r[q] = cn;
            float hn = tanhf(cn) * sigm(go);
            g_h[nb2][b * H_DIM + hcb + ehl] = __float2half(hn);
            if (t == S_LEN - 1) {
                out[b * H_DIM + hcb + ehl] = hn;
                out[BATCH * H_DIM + b * H_DIM + hcb + ehl] = cn;
            }
        }
        grid_sync(bar);
    }
}

// ---------------- host launch ----------------
extern "C" void kernel_launch(void* const* d_in, const int* in_sizes, int n_in,
                              void* d_out, int out_size) {
    const float* x  = (const float*)d_in[0];
    const float* h0 = (const float*)d_in[1];
    const float* c0 = (const float*)d_in[2];
    const float* Wx = (const float*)d_in[3];
    const float* Wh = (const float*)d_in[4];
    const float* bh = (const float*)d_in[5];
    float* out = (float*)d_out;

    prep_wxb<<<(G4 * D_IN + 255) / 256, 256>>>(Wx, bh);
    conv_x<<<(M_ROWS * D_IN + 511) / 512, 512>>>(x);
    prep_wrec<<<(NBLK * 36864 + 255) / 256, 256>>>(Wh);
    cudaFuncSetAttribute(gemm_gx, cudaFuncAttributeMaxDynamicSharedMemorySize, GSM_TOTAL);
    gemm_gx<<<dim3(G4 / 128, M_ROWS / 128), 512, GSM_TOTAL>>>();
    cudaFuncSetAttribute(lstm_rec, cudaFuncAttributeMaxDynamicSharedMemorySize, RSM_TOTAL);
    lstm_rec<<<NBLK, 256, RSM_TOTAL>>>(h0, c0, out);
}

// round 12
// speedup vs baseline: 1.4599x; 1.0893x over previous
#include <cuda_runtime.h>
#include <cuda_bf16.h>
#include <cuda_fp16.h>
#include <cstdint>

#define S_LEN 512
#define BATCH 64
#define D_IN  512
#define H_DIM 1024
#define G4    4096
#define M_ROWS 32768
#define NBLK  128

// ---- recurrence SMEM layout (bytes) ----
// W: 16 chunks x (32 rows x 144B), single fp16 image
#define RSM_H     73728             // 3 bufs x 9216 (single fp16 h image)
#define RSM_G     101376            // gates 64x32 f32
#define RSM_TOTAL 109568
// ---- gx GEMM SMEM: 3 bufs x 55296 (Ahi, Alo, B @ 18432 each) ----
#define GSM_BUF   55296
#define GSM_TOTAL 165888

// ---------------- device scratch ----------------
__device__ float g_bh_p[G4];
__device__ float g_gx[(size_t)M_ROWS * G4];
__device__ __half g_x16h[(size_t)M_ROWS * D_IN];        // x fp16 hi
__device__ __half g_x16l[(size_t)M_ROWS * D_IN];        // x fp16 lo (residual)
__device__ __half g_Wx16[(size_t)G4 * D_IN];            // Wx fp16, n-major, permuted
__device__ __half g_Wr[(size_t)NBLK * 36864];           // per-CTA padded W chunk images (fp16)
__device__ __half g_h[2][BATCH * H_DIM];                // single fp16 h image, ping-pong
__device__ unsigned g_bar_count, g_bar_gen;

// ---------------- helpers ----------------
__device__ __forceinline__ uint32_t smem_u32(const void* p) {
    uint32_t a;
    asm("{ .reg .u64 t; cvta.to.shared.u64 t, %1; cvt.u32.u64 %0, t; }" : "=r"(a) : "l"(p));
    return a;
}
__device__ __forceinline__ void ldm4(uint32_t a, uint32_t& r0, uint32_t& r1, uint32_t& r2, uint32_t& r3) {
    asm volatile("ldmatrix.sync.aligned.m8n8.x4.shared.b16 {%0,%1,%2,%3}, [%4];"
                 : "=r"(r0), "=r"(r1), "=r"(r2), "=r"(r3) : "r"(a));
}
__device__ __forceinline__ void mma_f16(float* c, uint32_t a0, uint32_t a1, uint32_t a2, uint32_t a3,
                                        uint32_t b0, uint32_t b1) {
    asm volatile("mma.sync.aligned.m16n8k16.row.col.f32.f16.f16.f32 "
                 "{%0,%1,%2,%3}, {%4,%5,%6,%7}, {%8,%9}, {%0,%1,%2,%3};"
                 : "+f"(c[0]), "+f"(c[1]), "+f"(c[2]), "+f"(c[3])
                 : "r"(a0), "r"(a1), "r"(a2), "r"(a3), "r"(b0), "r"(b1));
}
__device__ __forceinline__ void cp16(uint32_t dst, const void* src) {
    asm volatile("cp.async.cg.shared.global [%0], [%1], 16;" :: "r"(dst), "l"(src) : "memory");
}
__device__ __forceinline__ void cp_commit() { asm volatile("cp.async.commit_group;" ::: "memory"); }
__device__ __forceinline__ void cp_wait1()  { asm volatile("cp.async.wait_group 1;" ::: "memory"); }
__device__ __forceinline__ void cp_wait0()  { asm volatile("cp.async.wait_group 0;" ::: "memory"); }
__device__ __forceinline__ float sigm(float x) { return 1.0f / (1.0f + __expf(-x)); }

__device__ __forceinline__ void grid_sync(unsigned& bar) {
    __syncthreads();
    if (threadIdx.x == 0) {
        __threadfence();
        unsigned t = atomicAdd(&g_bar_count, 1u);
        bar += 1;
        if (t == gridDim.x - 1u) {
            atomicExch(&g_bar_count, 0u);
            __threadfence();
            atomicAdd(&g_bar_gen, 1u);
        } else {
            while ((int)(atomicAdd(&g_bar_gen, 0u) - bar) < 0) __nanosleep(64);
        }
    }
    __syncthreads();
}

// ---------------- prep: Wx -> n-major permuted fp16; bias ----------------
__global__ void prep_wxb(const float* __restrict__ Wx, const float* __restrict__ bh) {
    int idx = blockIdx.x * blockDim.x + threadIdx.x;      // 4096*512
    if (idx >= G4 * D_IN) return;
    int n = idx >> 9, k = idx & 511;
    float v = Wx[(size_t)k * G4 + (n & 3) * H_DIM + (n >> 2)];
    g_Wx16[idx] = __float2half(v);
    if (k == 0) g_bh_p[n] = bh[(n & 3) * H_DIM + (n >> 2)];
}

// ---------------- prep: x -> fp16 hi/lo pair ----------------
__global__ void conv_x(const float* __restrict__ x) {
    size_t idx = (size_t)blockIdx.x * blockDim.x + threadIdx.x;
    if (idx >= (size_t)M_ROWS * D_IN) return;
    float v = x[idx];
    __half hi = __float2half(v);
    g_x16h[idx] = hi;
    g_x16l[idx] = __float2half(v - __half2float(hi));
}

// ---------------- prep: per-CTA padded W chunk images (single fp16) ----------------
// image: 16 chunks x (32 n-rows x 72 elems [64 data + 8 pad])
__global__ void prep_wrec(const float* __restrict__ Wh) {
    size_t idx = (size_t)blockIdx.x * blockDim.x + threadIdx.x;
    if (idx >= (size_t)NBLK * 36864) return;
    int bid = (int)(idx / 36864);
    int e = (int)(idx % 36864);
    int c = e / 2304, rr = e % 2304;
    int n = rr / 72, k = rr % 72;
    __half hi = __float2half(0.f);
    if (k < 64) {
        int cn = bid * 32 + n;
        hi = __float2half(Wh[(size_t)(c * 64 + k) * G4 + (cn & 3) * H_DIM + (cn >> 2)]);
    }
    g_Wr[idx] = hi;
}

// ---------------- gx GEMM (mma.sync fp16 2-term): g_gx = x @ Wx_p ----------------
__global__ __launch_bounds__(512, 1) void gemm_gx() {
    extern __shared__ char smem[];
    const uint32_t sb = smem_u32(smem);
    const int tid = threadIdx.x, lane = tid & 31, w = tid >> 5;
    const int mB = blockIdx.y * 128, nB = blockIdx.x * 128;
    const int m0 = (w & 3) * 32, n0 = (w >> 2) * 32;

    float acc[2][4][4];
#pragma unroll
    for (int a = 0; a < 2; ++a)
#pragma unroll
        for (int b = 0; b < 4; ++b)
#pragma unroll
            for (int d = 0; d < 4; ++d) acc[a][b][d] = 0.f;

    uint32_t aoff[2], boff[2];
#pragma unroll
    for (int mt = 0; mt < 2; ++mt)
        aoff[mt] = (uint32_t)(m0 + mt * 16 + (lane & 15)) * 144u + (uint32_t)(lane >> 4) * 16u;
#pragma unroll
    for (int g = 0; g < 2; ++g)
        boff[g] = (uint32_t)(n0 + g * 16 + ((lane >> 4) << 3) + (lane & 7)) * 144u +
                  (uint32_t)((lane >> 3) & 1) * 16u;

// 3 arrays per buffer: Ahi @0, Alo @18432, B @36864; each chunk-K64 = 1024 cp16 per array
#define GX_ISSUE(ch, buf) do {                                                     \
    _Pragma("unroll")                                                              \
    for (int q = 0; q < 6; ++q) {                                                  \
        int id = tid + q * 512;                                                    \
        int arr = id >> 10, rem = id & 1023, row = rem >> 3, seg = rem & 7;        \
        uint32_t dst = sb + (uint32_t)(buf) * (uint32_t)GSM_BUF +                  \
                       (uint32_t)arr * 18432u +                                    \
                       (uint32_t)row * 144u + (uint32_t)seg * 16u;                 \
        const __half* src;                                                         \
        if (arr == 0)      src = g_x16h + (size_t)(mB + row) * 512;                \
        else if (arr == 1) src = g_x16l + (size_t)(mB + row) * 512;                \
        else               src = g_Wx16 + (size_t)(nB + row) * 512;                \
        cp16(dst, src + (ch) * 64 + seg * 8);                                      \
    }                                                                              \
    cp_commit();                                                                   \
} while (0)

    GX_ISSUE(0, 0);
    GX_ISSUE(1, 1);
    for (int c = 0; c < 8; ++c) {
        if (c < 7) cp_wait1(); else cp_wait0();
        __syncthreads();
        const uint32_t base = sb + (uint32_t)(c % 3) * (uint32_t)GSM_BUF;
#pragma unroll
        for (int kk = 0; kk < 4; ++kk) {
            const uint32_t o = kk * 32;
            uint32_t ah[2][4], al[2][4], bv[2][4];
#pragma unroll
            for (int mt = 0; mt < 2; ++mt) {
                ldm4(base + aoff[mt] + o, ah[mt][0], ah[mt][1], ah[mt][2], ah[mt][3]);
                ldm4(base + 18432u + aoff[mt] + o, al[mt][0], al[mt][1], al[mt][2], al[mt][3]);
            }
#pragma unroll
            for (int g = 0; g < 2; ++g)
                ldm4(base + 36864u + boff[g] + o, bv[g][0], bv[g][1], bv[g][2], bv[g][3]);
            // term-major: x_hi * W then x_lo * W (independent spacing on same accumulators)
#pragma unroll
            for (int mt = 0; mt < 2; ++mt)
#pragma unroll
                for (int g = 0; g < 2; ++g) {
                    mma_f16(acc[mt][g * 2],     ah[mt][0], ah[mt][1], ah[mt][2], ah[mt][3], bv[g][0], bv[g][1]);
                    mma_f16(acc[mt][g * 2 + 1], ah[mt][0], ah[mt][1], ah[mt][2], ah[mt][3], bv[g][2], bv[g][3]);
                }
#pragma unroll
            for (int mt = 0; mt < 2; ++mt)
#pragma unroll
                for (int g = 0; g < 2; ++g) {
                    mma_f16(acc[mt][g * 2],     al[mt][0], al[mt][1], al[mt][2], al[mt][3], bv[g][0], bv[g][1]);
                    mma_f16(acc[mt][g * 2 + 1], al[mt][0], al[mt][1], al[mt][2], al[mt][3], bv[g][2], bv[g][3]);
                }
        }
        __syncthreads();
        if (c < 6) GX_ISSUE(c + 2, (c + 2) % 3);
    }
#undef GX_ISSUE
#pragma unroll
    for (int mt = 0; mt < 2; ++mt)
#pragma unroll
        for (int g = 0; g < 2; ++g)
#pragma unroll
            for (int hf = 0; hf < 2; ++hf) {
                int m = mB + m0 + mt * 16 + (lane >> 2);
                int n = nB + n0 + g * 16 + hf * 8 + (lane & 3) * 2;
                float* f = acc[mt][g * 2 + hf];
                *(float2*)&g_gx[(size_t)m * G4 + n] = make_float2(f[0], f[1]);
                *(float2*)&g_gx[(size_t)(m + 8) * G4 + n] = make_float2(f[2], f[3]);
            }
}

// ---------------- persistent mma.sync recurrence (fp16 single-W) ----------------
__global__ __launch_bounds__(256, 1) void lstm_rec(const float* __restrict__ h0,
                                                   const float* __restrict__ c0,
                                                   float* __restrict__ out) {
    extern __shared__ char smem[];
    const uint32_t sb = smem_u32(smem);
    const int tid = threadIdx.x, lane = tid & 31, w = tid >> 5, bid = blockIdx.x;
    const int hcb = bid * 8;
    const int m0 = (w & 3) * 16, n0 = (w >> 2) * 16;

    // resident W slice (single fp16)
    {
        const int4* sw = (const int4*)(g_Wr + (size_t)bid * 36864);
        int4* dw = (int4*)smem;
        for (int i = tid; i < 4608; i += 256) dw[i] = sw[i];
    }
    // h0 -> fp16 ping buffer 0 (disjoint slice per CTA)
    for (int i = tid; i < 512; i += 256) {
        int p = bid * 512 + i;
        g_h[0][p] = __float2half(h0[p]);
    }
    // per-thread cell state + bias
    const int eb = tid >> 3, ehl = tid & 7;
    float c_r[2];
    c_r[0] = c0[eb * H_DIM + hcb + ehl];
    c_r[1] = c0[(eb + 32) * H_DIM + hcb + ehl];
    const float4 br = *(const float4*)&g_bh_p[bid * 32 + ehl * 4];

    const uint32_t a_off = (uint32_t)(m0 + (lane & 15)) * 144u + (uint32_t)(lane >> 4) * 16u;
    const uint32_t b_off = (uint32_t)(n0 + ((lane >> 4) << 3) + (lane & 7)) * 144u +
                           (uint32_t)((lane >> 3) & 1) * 16u;

    unsigned bar = 0;
    if (tid == 0) bar = atomicAdd(&g_bar_gen, 0u);
    grid_sync(bar);

    for (int t = 0; t < S_LEN; ++t) {
        const int nb = t & 1;
        // prefetch gx (raw, bias added below)
        float4 gv0 = *(const float4*)&g_gx[(size_t)(t * BATCH + eb) * G4 + bid * 32 + ehl * 4];
        float4 gv1 = *(const float4*)&g_gx[(size_t)(t * BATCH + eb + 32) * G4 + bid * 32 + ehl * 4];

        // 2 independent accumulators (n-halves)
        float a0[4] = {0.f, 0.f, 0.f, 0.f};
        float a1[4] = {0.f, 0.f, 0.f, 0.f};

#define H_ISSUE(ch, buf) do {                                                      \
    _Pragma("unroll")                                                              \
    for (int q = 0; q < 2; ++q) {                                                  \
        int id = tid + q * 256;                                                    \
        int row = id >> 3, seg = id & 7;                                           \
        uint32_t dst = sb + RSM_H + (uint32_t)(buf) * 9216u +                      \
                       (uint32_t)row * 144u + (uint32_t)seg * 16u;                 \
        const __half* src = g_h[nb] + row * H_DIM + (ch) * 64 + seg * 8;           \
        cp16(dst, src);                                                            \
    }                                                                              \
    cp_commit();                                                                   \
} while (0)

        H_ISSUE(0, 0);
        H_ISSUE(1, 1);
        for (int c = 0; c < 16; ++c) {
            if (c < 15) cp_wait1(); else cp_wait0();
            __syncthreads();
            const uint32_t ah = sb + RSM_H + (uint32_t)(c % 3) * 9216u + a_off;
            const uint32_t bh = sb + (uint32_t)c * 4608u + b_off;
#pragma unroll
            for (int kk = 0; kk < 4; ++kk) {
                const uint32_t o = kk * 32;
                uint32_t A0, A1, A2, A3;
                uint32_t B0, B1, B2, B3;
                ldm4(ah + o, A0, A1, A2, A3);
                ldm4(bh + o, B0, B1, B2, B3);
                mma_f16(a0, A0, A1, A2, A3, B0, B1);
                mma_f16(a1, A0, A1, A2, A3, B2, B3);
            }
            if (c < 14) H_ISSUE(c + 2, (c + 2) % 3);
        }
#undef H_ISSUE

        // stage gates
        {
            float* G = (float*)(smem + RSM_G);
            int r0 = m0 + (lane >> 2), cb0 = n0 + (lane & 3) * 2;
            *(float2*)&G[r0 * 32 + cb0]           = make_float2(a0[0], a0[1]);
            *(float2*)&G[(r0 + 8) * 32 + cb0]     = make_float2(a0[2], a0[3]);
            *(float2*)&G[r0 * 32 + cb0 + 8]       = make_float2(a1[0], a1[1]);
            *(float2*)&G[(r0 + 8) * 32 + cb0 + 8] = make_float2(a1[2], a1[3]);
        }
        __syncthreads();

        // elementwise LSTM for (eb, ehl) and (eb+32, ehl)
        const int nb2 = nb ^ 1;
        const float* G = (const float*)(smem + RSM_G);
#pragma unroll
        for (int q = 0; q < 2; ++q) {
            int b = eb + q * 32;
            float4 gr = *(const float4*)&G[b * 32 + ehl * 4];
            float4 gx = q ? gv1 : gv0;
            float gi = gr.x + gx.x + br.x;
            float gf = gr.y + gx.y + br.y;
            float gj = gr.z + gx.z + br.z;
            float go = gr.w + gx.w + br.w;
            float cn = c_r[q] * sigm(gf + 1.0f) + sigm(gi) * tanhf(gj);
            c_r[q] = cn;
            float hn = tanhf(cn) * sigm(go);
            g_h[nb2][b * H_DIM + hcb + ehl] = __float2half(hn);
            if (t == S_LEN - 1) {
                out[b * H_DIM + hcb + ehl] = hn;
                out[BATCH * H_DIM + b * H_DIM + hcb + ehl] = cn;
            }
        }
        grid_sync(bar);
    }
}

// ---------------- host launch ----------------
extern "C" void kernel_launch(void* const* d_in, const int* in_sizes, int n_in,
                              void* d_out, int out_size) {
    const float* x  = (const float*)d_in[0];
    const float* h0 = (const float*)d_in[1];
    const float* c0 = (const float*)d_in[2];
    const float* Wx = (const float*)d_in[3];
    const float* Wh = (const float*)d_in[4];
    const float* bh = (const float*)d_in[5];
    float* out = (float*)d_out;

    prep_wxb<<<(G4 * D_IN + 255) / 256, 256>>>(Wx, bh);
    conv_x<<<(M_ROWS * D_IN + 511) / 512, 512>>>(x);
    prep_wrec<<<(NBLK * 36864 + 255) / 256, 256>>>(Wh);
    cudaFuncSetAttribute(gemm_gx, cudaFuncAttributeMaxDynamicSharedMemorySize, GSM_TOTAL);
    gemm_gx<<<dim3(G4 / 128, M_ROWS / 128), 512, GSM_TOTAL>>>();
    cudaFuncSetAttribute(lstm_rec, cudaFuncAttributeMaxDynamicSharedMemorySize, RSM_TOTAL);
    lstm_rec<<<NBLK, 256, RSM_TOTAL>>>(h0, c0, out);
}

// round 13
// speedup vs baseline: 1.5460x; 1.0590x over previous
#include <cuda_runtime.h>
#include <cuda_bf16.h>
#include <cuda_fp16.h>
#include <cstdint>

#define S_LEN 512
#define BATCH 64
#define D_IN  512
#define H_DIM 1024
#define G4    4096
#define M_ROWS 32768
#define NBLK  128

// ---- recurrence SMEM layout (bytes) ----
// W: 16 chunks x (32 rows x 144B), single fp16 image
#define RSM_H     73728             // 3 bufs x 9216 (single fp16 h image)
#define RSM_G     101376            // gates 64x32 f32
#define RSM_TOTAL 109568
// ---- gx GEMM SMEM: 3 bufs x 36864 (A, B @ 18432 each) ----
#define GSM_BUF   36864
#define GSM_TOTAL 110592

// ---------------- device scratch ----------------
__device__ float g_bh_p[G4];
__device__ float g_gx[(size_t)M_ROWS * G4];
__device__ __half g_x16[(size_t)M_ROWS * D_IN];         // x fp16
__device__ __half g_Wx16[(size_t)G4 * D_IN];            // Wx fp16, n-major, permuted
__device__ __half g_Wr[(size_t)NBLK * 36864];           // per-CTA padded W chunk images (fp16)
__device__ __half g_h[2][BATCH * H_DIM];                // single fp16 h image, ping-pong
__device__ unsigned g_bar_count, g_bar_gen;

// ---------------- helpers ----------------
__device__ __forceinline__ uint32_t smem_u32(const void* p) {
    uint32_t a;
    asm("{ .reg .u64 t; cvta.to.shared.u64 t, %1; cvt.u32.u64 %0, t; }" : "=r"(a) : "l"(p));
    return a;
}
__device__ __forceinline__ void ldm4(uint32_t a, uint32_t& r0, uint32_t& r1, uint32_t& r2, uint32_t& r3) {
    asm volatile("ldmatrix.sync.aligned.m8n8.x4.shared.b16 {%0,%1,%2,%3}, [%4];"
                 : "=r"(r0), "=r"(r1), "=r"(r2), "=r"(r3) : "r"(a));
}
__device__ __forceinline__ void mma_f16(float* c, uint32_t a0, uint32_t a1, uint32_t a2, uint32_t a3,
                                        uint32_t b0, uint32_t b1) {
    asm volatile("mma.sync.aligned.m16n8k16.row.col.f32.f16.f16.f32 "
                 "{%0,%1,%2,%3}, {%4,%5,%6,%7}, {%8,%9}, {%0,%1,%2,%3};"
                 : "+f"(c[0]), "+f"(c[1]), "+f"(c[2]), "+f"(c[3])
                 : "r"(a0), "r"(a1), "r"(a2), "r"(a3), "r"(b0), "r"(b1));
}
__device__ __forceinline__ void cp16(uint32_t dst, const void* src) {
    asm volatile("cp.async.cg.shared.global [%0], [%1], 16;" :: "r"(dst), "l"(src) : "memory");
}
__device__ __forceinline__ void cp_commit() { asm volatile("cp.async.commit_group;" ::: "memory"); }
__device__ __forceinline__ void cp_wait1()  { asm volatile("cp.async.wait_group 1;" ::: "memory"); }
__device__ __forceinline__ void cp_wait0()  { asm volatile("cp.async.wait_group 0;" ::: "memory"); }
__device__ __forceinline__ float sigm(float x) { return 1.0f / (1.0f + __expf(-x)); }

__device__ __forceinline__ void grid_sync(unsigned& bar) {
    __syncthreads();
    if (threadIdx.x == 0) {
        __threadfence();
        unsigned t = atomicAdd(&g_bar_count, 1u);
        bar += 1;
        if (t == gridDim.x - 1u) {
            atomicExch(&g_bar_count, 0u);
            __threadfence();
            atomicAdd(&g_bar_gen, 1u);
        } else {
            while ((int)(atomicAdd(&g_bar_gen, 0u) - bar) < 0) __nanosleep(64);
        }
    }
    __syncthreads();
}

// ---------------- prep: Wx -> n-major permuted fp16; bias ----------------
__global__ void prep_wxb(const float* __restrict__ Wx, const float* __restrict__ bh) {
    int idx = blockIdx.x * blockDim.x + threadIdx.x;      // 4096*512
    if (idx >= G4 * D_IN) return;
    int n = idx >> 9, k = idx & 511;
    float v = Wx[(size_t)k * G4 + (n & 3) * H_DIM + (n >> 2)];
    g_Wx16[idx] = __float2half(v);
    if (k == 0) g_bh_p[n] = bh[(n & 3) * H_DIM + (n >> 2)];
}

// ---------------- prep: x -> fp16 ----------------
__global__ void conv_x(const float* __restrict__ x) {
    size_t idx = (size_t)blockIdx.x * blockDim.x + threadIdx.x;
    if (idx >= (size_t)M_ROWS * D_IN) return;
    g_x16[idx] = __float2half(x[idx]);
}

// ---------------- prep: per-CTA padded W chunk images (single fp16) ----------------
// image: 16 chunks x (32 n-rows x 72 elems [64 data + 8 pad])
__global__ void prep_wrec(const float* __restrict__ Wh) {
    size_t idx = (size_t)blockIdx.x * blockDim.x + threadIdx.x;
    if (idx >= (size_t)NBLK * 36864) return;
    int bid = (int)(idx / 36864);
    int e = (int)(idx % 36864);
    int c = e / 2304, rr = e % 2304;
    int n = rr / 72, k = rr % 72;
    __half hi = __float2half(0.f);
    if (k < 64) {
        int cn = bid * 32 + n;
        hi = __float2half(Wh[(size_t)(c * 64 + k) * G4 + (cn & 3) * H_DIM + (cn >> 2)]);
    }
    g_Wr[idx] = hi;
}

// ---------------- gx GEMM (mma.sync fp16 single-term): g_gx = x @ Wx_p ----------------
__global__ __launch_bounds__(512, 1) void gemm_gx() {
    extern __shared__ char smem[];
    const uint32_t sb = smem_u32(smem);
    const int tid = threadIdx.x, lane = tid & 31, w = tid >> 5;
    const int mB = blockIdx.y * 128, nB = blockIdx.x * 128;
    const int m0 = (w & 3) * 32, n0 = (w >> 2) * 32;

    float acc[2][4][4];
#pragma unroll
    for (int a = 0; a < 2; ++a)
#pragma unroll
        for (int b = 0; b < 4; ++b)
#pragma unroll
            for (int d = 0; d < 4; ++d) acc[a][b][d] = 0.f;

    uint32_t aoff[2], boff[2];
#pragma unroll
    for (int mt = 0; mt < 2; ++mt)
        aoff[mt] = (uint32_t)(m0 + mt * 16 + (lane & 15)) * 144u + (uint32_t)(lane >> 4) * 16u;
#pragma unroll
    for (int g = 0; g < 2; ++g)
        boff[g] = (uint32_t)(n0 + g * 16 + ((lane >> 4) << 3) + (lane & 7)) * 144u +
                  (uint32_t)((lane >> 3) & 1) * 16u;

// 2 arrays per buffer: A @0, B @18432; each chunk-K64 = 1024 cp16 per array
#define GX_ISSUE(ch, buf) do {                                                     \
    _Pragma("unroll")                                                              \
    for (int q = 0; q < 4; ++q) {                                                  \
        int id = tid + q * 512;                                                    \
        int arr = id >> 10, rem = id & 1023, row = rem >> 3, seg = rem & 7;        \
        uint32_t dst = sb + (uint32_t)(buf) * (uint32_t)GSM_BUF +                  \
                       (uint32_t)arr * 18432u +                                    \
                       (uint32_t)row * 144u + (uint32_t)seg * 16u;                 \
        const __half* src;                                                         \
        if (arr == 0) src = g_x16 + (size_t)(mB + row) * 512;                      \
        else          src = g_Wx16 + (size_t)(nB + row) * 512;                     \
        cp16(dst, src + (ch) * 64 + seg * 8);                                      \
    }                                                                              \
    cp_commit();                                                                   \
} while (0)

    GX_ISSUE(0, 0);
    GX_ISSUE(1, 1);
    for (int c = 0; c < 8; ++c) {
        if (c < 7) cp_wait1(); else cp_wait0();
        __syncthreads();
        const uint32_t base = sb + (uint32_t)(c % 3) * (uint32_t)GSM_BUF;
#pragma unroll
        for (int kk = 0; kk < 4; ++kk) {
            const uint32_t o = kk * 32;
            uint32_t av[2][4], bv[2][4];
#pragma unroll
            for (int mt = 0; mt < 2; ++mt)
                ldm4(base + aoff[mt] + o, av[mt][0], av[mt][1], av[mt][2], av[mt][3]);
#pragma unroll
            for (int g = 0; g < 2; ++g)
                ldm4(base + 18432u + boff[g] + o, bv[g][0], bv[g][1], bv[g][2], bv[g][3]);
#pragma unroll
            for (int mt = 0; mt < 2; ++mt)
#pragma unroll
                for (int g = 0; g < 2; ++g) {
                    mma_f16(acc[mt][g * 2],     av[mt][0], av[mt][1], av[mt][2], av[mt][3], bv[g][0], bv[g][1]);
                    mma_f16(acc[mt][g * 2 + 1], av[mt][0], av[mt][1], av[mt][2], av[mt][3], bv[g][2], bv[g][3]);
                }
        }
        __syncthreads();
        if (c < 6) GX_ISSUE(c + 2, (c + 2) % 3);
    }
#undef GX_ISSUE
#pragma unroll
    for (int mt = 0; mt < 2; ++mt)
#pragma unroll
        for (int g = 0; g < 2; ++g)
#pragma unroll
            for (int hf = 0; hf < 2; ++hf) {
                int m = mB + m0 + mt * 16 + (lane >> 2);
                int n = nB + n0 + g * 16 + hf * 8 + (lane & 3) * 2;
                float* f = acc[mt][g * 2 + hf];
                *(float2*)&g_gx[(size_t)m * G4 + n] = make_float2(f[0], f[1]);
                *(float2*)&g_gx[(size_t)(m + 8) * G4 + n] = make_float2(f[2], f[3]);
            }
}

// ---------------- persistent mma.sync recurrence (fp16 single-W) ----------------
__global__ __launch_bounds__(256, 1) void lstm_rec(const float* __restrict__ h0,
                                                   const float* __restrict__ c0,
                                                   float* __restrict__ out) {
    extern __shared__ char smem[];
    const uint32_t sb = smem_u32(smem);
    const int tid = threadIdx.x, lane = tid & 31, w = tid >> 5, bid = blockIdx.x;
    const int hcb = bid * 8;
    const int m0 = (w & 3) * 16, n0 = (w >> 2) * 16;

    // resident W slice (single fp16)
    {
        const int4* sw = (const int4*)(g_Wr + (size_t)bid * 36864);
        int4* dw = (int4*)smem;
        for (int i = tid; i < 4608; i += 256) dw[i] = sw[i];
    }
    // h0 -> fp16 ping buffer 0 (disjoint slice per CTA)
    for (int i = tid; i < 512; i += 256) {
        int p = bid * 512 + i;
        g_h[0][p] = __float2half(h0[p]);
    }
    // per-thread cell state + bias
    const int eb = tid >> 3, ehl = tid & 7;
    float c_r[2];
    c_r[0] = c0[eb * H_DIM + hcb + ehl];
    c_r[1] = c0[(eb + 32) * H_DIM + hcb + ehl];
    const float4 br = *(const float4*)&g_bh_p[bid * 32 + ehl * 4];

    const uint32_t a_off = (uint32_t)(m0 + (lane & 15)) * 144u + (uint32_t)(lane >> 4) * 16u;
    const uint32_t b_off = (uint32_t)(n0 + ((lane >> 4) << 3) + (lane & 7)) * 144u +
                           (uint32_t)((lane >> 3) & 1) * 16u;

    unsigned bar = 0;
    if (tid == 0) bar = atomicAdd(&g_bar_gen, 0u);
    grid_sync(bar);

    for (int t = 0; t < S_LEN; ++t) {
        const int nb = t & 1;
        // prefetch gx (raw, bias added below)
        float4 gv0 = *(const float4*)&g_gx[(size_t)(t * BATCH + eb) * G4 + bid * 32 + ehl * 4];
        float4 gv1 = *(const float4*)&g_gx[(size_t)(t * BATCH + eb + 32) * G4 + bid * 32 + ehl * 4];

        // 2 independent accumulators (n-halves)
        float a0[4] = {0.f, 0.f, 0.f, 0.f};
        float a1[4] = {0.f, 0.f, 0.f, 0.f};

#define H_ISSUE(ch, buf) do {                                                      \
    _Pragma("unroll")                                                              \
    for (int q = 0; q < 2; ++q) {                                                  \
        int id = tid + q * 256;                                                    \
        int row = id >> 3, seg = id & 7;                                           \
        uint32_t dst = sb + RSM_H + (uint32_t)(buf) * 9216u +                      \
                       (uint32_t)row * 144u + (uint32_t)seg * 16u;                 \
        const __half* src = g_h[nb] + row * H_DIM + (ch) * 64 + seg * 8;           \
        cp16(dst, src);                                                            \
    }                                                                              \
    cp_commit();                                                                   \
} while (0)

        H_ISSUE(0, 0);
        H_ISSUE(1, 1);
        for (int c = 0; c < 16; ++c) {
            if (c < 15) cp_wait1(); else cp_wait0();
            __syncthreads();
            const uint32_t ah = sb + RSM_H + (uint32_t)(c % 3) * 9216u + a_off;
            const uint32_t bh = sb + (uint32_t)c * 4608u + b_off;
#pragma unroll
            for (int kk = 0; kk < 4; ++kk) {
                const uint32_t o = kk * 32;
                uint32_t A0, A1, A2, A3;
                uint32_t B0, B1, B2, B3;
                ldm4(ah + o, A0, A1, A2, A3);
                ldm4(bh + o, B0, B1, B2, B3);
                mma_f16(a0, A0, A1, A2, A3, B0, B1);
                mma_f16(a1, A0, A1, A2, A3, B2, B3);
            }
            if (c < 14) H_ISSUE(c + 2, (c + 2) % 3);
        }
#undef H_ISSUE

        // stage gates
        {
            float* G = (float*)(smem + RSM_G);
            int r0 = m0 + (lane >> 2), cb0 = n0 + (lane & 3) * 2;
            *(float2*)&G[r0 * 32 + cb0]           = make_float2(a0[0], a0[1]);
            *(float2*)&G[(r0 + 8) * 32 + cb0]     = make_float2(a0[2], a0[3]);
            *(float2*)&G[r0 * 32 + cb0 + 8]       = make_float2(a1[0], a1[1]);
            *(float2*)&G[(r0 + 8) * 32 + cb0 + 8] = make_float2(a1[2], a1[3]);
        }
        __syncthreads();

        // elementwise LSTM for (eb, ehl) and (eb+32, ehl)
        const int nb2 = nb ^ 1;
        const float* G = (const float*)(smem + RSM_G);
#pragma unroll
        for (int q = 0; q < 2; ++q) {
            int b = eb + q * 32;
            float4 gr = *(const float4*)&G[b * 32 + ehl * 4];
            float4 gx = q ? gv1 : gv0;
            float gi = gr.x + gx.x + br.x;
            float gf = gr.y + gx.y + br.y;
            float gj = gr.z + gx.z + br.z;
            float go = gr.w + gx.w + br.w;
            float cn = c_r[q] * sigm(gf + 1.0f) + sigm(gi) * tanhf(gj);
            c_r[q] = cn;
            float hn = tanhf(cn) * sigm(go);
            g_h[nb2][b * H_DIM + hcb + ehl] = __float2half(hn);
            if (t == S_LEN - 1) {
                out[b * H_DIM + hcb + ehl] = hn;
                out[BATCH * H_DIM + b * H_DIM + hcb + ehl] = cn;
            }
        }
        grid_sync(bar);
    }
}

// ---------------- host launch ----------------
extern "C" void kernel_launch(void* const* d_in, const int* in_sizes, int n_in,
                              void* d_out, int out_size) {
    const float* x  = (const float*)d_in[0];
    const float* h0 = (const float*)d_in[1];
    const float* c0 = (const float*)d_in[2];
    const float* Wx = (const float*)d_in[3];
    const float* Wh = (const float*)d_in[4];
    const float* bh = (const float*)d_in[5];
    float* out = (float*)d_out;

    prep_wxb<<<(G4 * D_IN + 255) / 256, 256>>>(Wx, bh);
    conv_x<<<(M_ROWS * D_IN + 511) / 512, 512>>>(x);
    prep_wrec<<<(NBLK * 36864 + 255) / 256, 256>>>(Wh);
    cudaFuncSetAttribute(gemm_gx, cudaFuncAttributeMaxDynamicSharedMemorySize, GSM_TOTAL);
    gemm_gx<<<dim3(G4 / 128, M_ROWS / 128), 512, GSM_TOTAL>>>();
    cudaFuncSetAttribute(lstm_rec, cudaFuncAttributeMaxDynamicSharedMemorySize, RSM_TOTAL);
    lstm_rec<<<NBLK, 256, RSM_TOTAL>>>(h0, c0, out);
}